// round 11
// baseline (speedup 1.0000x reference)
#include <cuda_runtime.h>
#include <math.h>

#define NJ    400000
#define F     128
#define NBLK  888            // 6 blocks/SM x 148 SMs (one wave); 888 = 2*444
#define TPB   256
#define WPB   (TPB / 32)
#define NW    (NBLK * WPB)

// Scratch (allocation-free rule: __device__ globals)
__device__ float g_pv[8 * F];
__device__ float g_c0;
__device__ float g_m[NBLK];
__device__ float g_s[NBLK];
__device__ float g_u[NBLK * F];
__device__ unsigned int g_cnt;

// ---------------------------------------------------------------------------
// Kernel A: precompute, grid = 9 blocks x 1024 threads (proven ~3us).
// ---------------------------------------------------------------------------
__global__ void __launch_bounds__(1024) prep_kernel(
        const float* __restrict__ h_i,
        const float* __restrict__ W_i_w,
        const float* __restrict__ W_i_b,
        const float* __restrict__ W_j_w,
        const float* __restrict__ W_j_b,
        const float* __restrict__ W_ij) {
    const int tid  = threadIdx.x;
    const int b    = blockIdx.x;

    if (b < 8) {
        __shared__ float s_p[8 * F];
        const int t   = tid & 127;
        const int sub = tid >> 7;
        const int f0  = b * 16 + sub * 2;
        float acc = W_j_w[f0 * F + t]       * W_ij[F + f0]
                  + W_j_w[(f0 + 1) * F + t] * W_ij[F + f0 + 1];
        s_p[sub * F + t] = acc;
        __syncthreads();
        if (tid < F) {
            float v = 0.f;
#pragma unroll
            for (int s = 0; s < 8; s++) v += s_p[s * F + tid];
            g_pv[b * F + tid] = v;
        }
        return;
    }

    __shared__ __align__(16) float s_hi[F];
    __shared__ float s_z[F];
    __shared__ float s_red[F];
    const int wid  = tid >> 5;
    const int lane = tid & 31;

    if (tid == 0) g_cnt = 0u;
    if (tid < F) s_hi[tid] = h_i[tid];
    __syncthreads();

    const float4 hv = reinterpret_cast<const float4*>(s_hi)[lane];
    const float4 w0 = reinterpret_cast<const float4*>(W_i_w + (wid      ) * F)[lane];
    const float4 w1 = reinterpret_cast<const float4*>(W_i_w + (wid + 32 ) * F)[lane];
    const float4 w2 = reinterpret_cast<const float4*>(W_i_w + (wid + 64 ) * F)[lane];
    const float4 w3 = reinterpret_cast<const float4*>(W_i_w + (wid + 96 ) * F)[lane];
    float d0 = w0.x*hv.x + w0.y*hv.y + w0.z*hv.z + w0.w*hv.w;
    float d1 = w1.x*hv.x + w1.y*hv.y + w1.z*hv.z + w1.w*hv.w;
    float d2 = w2.x*hv.x + w2.y*hv.y + w2.z*hv.z + w2.w*hv.w;
    float d3 = w3.x*hv.x + w3.y*hv.y + w3.z*hv.z + w3.w*hv.w;
#pragma unroll
    for (int off = 16; off > 0; off >>= 1) {
        d0 += __shfl_xor_sync(0xffffffffu, d0, off);
        d1 += __shfl_xor_sync(0xffffffffu, d1, off);
        d2 += __shfl_xor_sync(0xffffffffu, d2, off);
        d3 += __shfl_xor_sync(0xffffffffu, d3, off);
    }
    if (lane == 0) {
        s_z[wid     ] = d0 + W_i_b[wid     ];
        s_z[wid + 32] = d1 + W_i_b[wid + 32];
        s_z[wid + 64] = d2 + W_i_b[wid + 64];
        s_z[wid + 96] = d3 + W_i_b[wid + 96];
    }
    __syncthreads();

    if (tid < F) s_red[tid] = W_ij[tid] * s_z[tid] + W_j_b[tid] * W_ij[F + tid];
    __syncthreads();
    if (tid < 64) s_red[tid] += s_red[tid + 64];
    __syncthreads();
    if (tid < 32) {
        float c = s_red[tid] + s_red[tid + 32];
#pragma unroll
        for (int off = 16; off > 0; off >>= 1)
            c += __shfl_xor_sync(0xffffffffu, c, off);
        if (tid == 0) g_c0 = c;
    }
}

// ---------------------------------------------------------------------------
// Kernel B: R2's measured-best streaming loop (1 row/warp/iter, eager
// branch-free online softmax, 1-ahead prefetch) + fused last-block finalize.
// ---------------------------------------------------------------------------
__global__ void __launch_bounds__(TPB) pass_kernel(
        const float* __restrict__ h_j,
        const float* __restrict__ W_j_w,
        const float* __restrict__ W_j_b,
        float* __restrict__ out) {
    __shared__ __align__(16) float sv[F];
    __shared__ float red_m[WPB];
    __shared__ float red_s[WPB];
    __shared__ float red_u[WPB * F];
    __shared__ float s_mb;

    if (threadIdx.x < F) {
        float v = 0.f;
#pragma unroll
        for (int s = 0; s < 8; s++) v += g_pv[s * F + threadIdx.x];
        sv[threadIdx.x] = v;
    }
    __syncthreads();

    const float c0   = g_c0;
    const int  warp  = threadIdx.x >> 5;
    const int  lane  = threadIdx.x & 31;
    const int  gw    = blockIdx.x * WPB + warp;

    const float4 vv = reinterpret_cast<const float4*>(sv)[lane];
    const float4* __restrict__ hj4 = reinterpret_cast<const float4*>(h_j);

    float m = -1e30f, ssum = 0.f;
    float ux = 0.f, uy = 0.f, uz = 0.f, uw = 0.f;

    int row = gw;
    float4 x = make_float4(0.f, 0.f, 0.f, 0.f);
    if (row < NJ) x = __ldg(hj4 + (size_t)row * 32 + lane);

    while (row < NJ) {
        const int nrow = row + NW;
        float4 xn = x;
        if (nrow < NJ) xn = __ldg(hj4 + (size_t)nrow * 32 + lane);

        float d = x.x * vv.x + x.y * vv.y + x.z * vv.z + x.w * vv.w;
        d += __shfl_xor_sync(0xffffffffu, d, 16);
        d += __shfl_xor_sync(0xffffffffu, d, 8);
        d += __shfl_xor_sync(0xffffffffu, d, 4);
        d += __shfl_xor_sync(0xffffffffu, d, 2);
        d += __shfl_xor_sync(0xffffffffu, d, 1);

        const float s = d + c0;
        const float e = (s > 0.f) ? s : 0.1f * s;

        const float mn    = fmaxf(m, e);
        const float scale = __expf(m - mn);
        const float w     = __expf(e - mn);
        ssum = ssum * scale + w;
        ux   = ux * scale + w * x.x;
        uy   = uy * scale + w * x.y;
        uz   = uz * scale + w * x.z;
        uw   = uw * scale + w * x.w;
        m = mn;

        x = xn;
        row = nrow;
    }

    // ---- block combine ----
    if (lane == 0) { red_m[warp] = m; red_s[warp] = ssum; }
    red_u[warp * F + lane * 4 + 0] = ux;
    red_u[warp * F + lane * 4 + 1] = uy;
    red_u[warp * F + lane * 4 + 2] = uz;
    red_u[warp * F + lane * 4 + 3] = uw;
    __syncthreads();

    if (threadIdx.x == 0) {
        float mb = red_m[0];
#pragma unroll
        for (int w2 = 1; w2 < WPB; w2++) mb = fmaxf(mb, red_m[w2]);
        s_mb = mb;
    }
    __syncthreads();
    const float mb = s_mb;

    const int t = threadIdx.x;
    if (t < F) {
        float acc = 0.f;
#pragma unroll
        for (int w2 = 0; w2 < WPB; w2++)
            acc += __expf(red_m[w2] - mb) * red_u[w2 * F + t];
        g_u[blockIdx.x * F + t] = acc;
    }
    if (t == 0) {
        float sb = 0.f;
#pragma unroll
        for (int w2 = 0; w2 < WPB; w2++) sb += __expf(red_m[w2] - mb) * red_s[w2];
        g_s[blockIdx.x] = sb;
        g_m[blockIdx.x] = mb;
    }
    __syncthreads();

    // ---- last-block fused finalize ----
    __shared__ unsigned int s_last;
    __threadfence();
    if (threadIdx.x == 0)
        s_last = (atomicAdd(&g_cnt, 1u) == (unsigned)(NBLK - 1)) ? 1u : 0u;
    __syncthreads();
    if (!s_last) return;

    __shared__ float sf[NBLK];
    __shared__ float s_pu[2 * F];
    __shared__ __align__(16) float sun[F];
    __shared__ float s_r[WPB];
    __shared__ float s_mg, s_S;

    // global max over NBLK block maxima
    {
        float lm = -1e30f;
        for (int b = t; b < NBLK; b += TPB) lm = fmaxf(lm, g_m[b]);
#pragma unroll
        for (int off = 16; off > 0; off >>= 1)
            lm = fmaxf(lm, __shfl_xor_sync(0xffffffffu, lm, off));
        if (lane == 0) s_r[warp] = lm;
        __syncthreads();
        if (t == 0) {
            float v = s_r[0];
#pragma unroll
            for (int w2 = 1; w2 < WPB; w2++) v = fmaxf(v, s_r[w2]);
            s_mg = v;
        }
        __syncthreads();
    }
    const float mg = s_mg;

    // scale factors + global sum
    {
        float ls = 0.f;
        for (int b = t; b < NBLK; b += TPB) {
            const float fct = __expf(g_m[b] - mg);
            sf[b] = fct;
            ls += fct * g_s[b];
        }
#pragma unroll
        for (int off = 16; off > 0; off >>= 1)
            ls += __shfl_xor_sync(0xffffffffu, ls, off);
        if (lane == 0) s_r[warp] = ls;
        __syncthreads();
        if (t == 0) {
            float v = 0.f;
#pragma unroll
            for (int w2 = 0; w2 < WPB; w2++) v += s_r[w2];
            s_S = v;
        }
        __syncthreads();
    }
    const float S = s_S;

    // combine u partials: 2 slices x 128 features (888 = 2*444), L2-hot
    {
        const int slice = t >> 7;
        const int tf    = t & 127;
        const int b0    = slice * 444;
        float acc = 0.f;
#pragma unroll 4
        for (int k = 0; k < 444; k++)
            acc += sf[b0 + k] * g_u[(b0 + k) * F + tf];
        s_pu[slice * F + tf] = acc;
    }
    __syncthreads();
    if (t < F) sun[t] = (s_pu[t] + s_pu[F + t]) / S;
    __syncthreads();

    // h = W_j_w @ u_norm + b : warp-per-row, 16 rows per warp
    const float4 uv = reinterpret_cast<const float4*>(sun)[lane];
#pragma unroll 4
    for (int r = 0; r < 16; r++) {
        const int f = warp + WPB * r;
        const float4 wrow = reinterpret_cast<const float4*>(W_j_w + f * F)[lane];
        float d = wrow.x*uv.x + wrow.y*uv.y + wrow.z*uv.z + wrow.w*uv.w;
#pragma unroll
        for (int off = 16; off > 0; off >>= 1)
            d += __shfl_xor_sync(0xffffffffu, d, off);
        if (lane == 0) {
            const float h = d + W_j_b[f];
            out[f] = (h > 0.f) ? h : expm1f(h);
        }
    }
}

// ---------------------------------------------------------------------------
extern "C" void kernel_launch(void* const* d_in, const int* in_sizes, int n_in,
                              void* d_out, int out_size) {
    const float* h_i   = (const float*)d_in[0];
    const float* h_j   = (const float*)d_in[1];
    const float* W_i_w = (const float*)d_in[2];
    const float* W_i_b = (const float*)d_in[3];
    const float* W_j_w = (const float*)d_in[4];
    const float* W_j_b = (const float*)d_in[5];
    const float* W_ij  = (const float*)d_in[6];
    float* out = (float*)d_out;

    prep_kernel<<<9, 1024>>>(h_i, W_i_w, W_i_b, W_j_w, W_j_b, W_ij);
    pass_kernel<<<NBLK, TPB>>>(h_j, W_j_w, W_j_b, out);
}

// round 12
// speedup vs baseline: 1.0004x; 1.0004x over previous
#include <cuda_runtime.h>
#include <math.h>

#define NJ    400000
#define F     128
#define NBLK  888            // 6 blocks/SM x 148 SMs (one wave); 888 = 2*444
#define TPB   256
#define WPB   (TPB / 32)
#define NW    (NBLK * WPB)

// Scratch (allocation-free rule: __device__ globals)
__device__ float g_pv[8 * F];
__device__ float g_c0;
__device__ float g_m[NBLK];
__device__ float g_s[NBLK];
__device__ float g_u[NBLK * F];
__device__ unsigned int g_cnt;

// ---------------------------------------------------------------------------
// Kernel A: precompute, grid = 9 blocks x 1024 threads (proven ~3us).
// ---------------------------------------------------------------------------
__global__ void __launch_bounds__(1024) prep_kernel(
        const float* __restrict__ h_i,
        const float* __restrict__ W_i_w,
        const float* __restrict__ W_i_b,
        const float* __restrict__ W_j_w,
        const float* __restrict__ W_j_b,
        const float* __restrict__ W_ij) {
    const int tid  = threadIdx.x;
    const int b    = blockIdx.x;

    if (b < 8) {
        __shared__ float s_p[8 * F];
        const int t   = tid & 127;
        const int sub = tid >> 7;
        const int f0  = b * 16 + sub * 2;
        float acc = W_j_w[f0 * F + t]       * W_ij[F + f0]
                  + W_j_w[(f0 + 1) * F + t] * W_ij[F + f0 + 1];
        s_p[sub * F + t] = acc;
        __syncthreads();
        if (tid < F) {
            float v = 0.f;
#pragma unroll
            for (int s = 0; s < 8; s++) v += s_p[s * F + tid];
            g_pv[b * F + tid] = v;
        }
        return;
    }

    __shared__ __align__(16) float s_hi[F];
    __shared__ float s_z[F];
    __shared__ float s_red[F];
    const int wid  = tid >> 5;
    const int lane = tid & 31;

    if (tid == 0) g_cnt = 0u;
    if (tid < F) s_hi[tid] = h_i[tid];
    __syncthreads();

    const float4 hv = reinterpret_cast<const float4*>(s_hi)[lane];
    const float4 w0 = reinterpret_cast<const float4*>(W_i_w + (wid      ) * F)[lane];
    const float4 w1 = reinterpret_cast<const float4*>(W_i_w + (wid + 32 ) * F)[lane];
    const float4 w2 = reinterpret_cast<const float4*>(W_i_w + (wid + 64 ) * F)[lane];
    const float4 w3 = reinterpret_cast<const float4*>(W_i_w + (wid + 96 ) * F)[lane];
    float d0 = w0.x*hv.x + w0.y*hv.y + w0.z*hv.z + w0.w*hv.w;
    float d1 = w1.x*hv.x + w1.y*hv.y + w1.z*hv.z + w1.w*hv.w;
    float d2 = w2.x*hv.x + w2.y*hv.y + w2.z*hv.z + w2.w*hv.w;
    float d3 = w3.x*hv.x + w3.y*hv.y + w3.z*hv.z + w3.w*hv.w;
#pragma unroll
    for (int off = 16; off > 0; off >>= 1) {
        d0 += __shfl_xor_sync(0xffffffffu, d0, off);
        d1 += __shfl_xor_sync(0xffffffffu, d1, off);
        d2 += __shfl_xor_sync(0xffffffffu, d2, off);
        d3 += __shfl_xor_sync(0xffffffffu, d3, off);
    }
    if (lane == 0) {
        s_z[wid     ] = d0 + W_i_b[wid     ];
        s_z[wid + 32] = d1 + W_i_b[wid + 32];
        s_z[wid + 64] = d2 + W_i_b[wid + 64];
        s_z[wid + 96] = d3 + W_i_b[wid + 96];
    }
    __syncthreads();

    if (tid < F) s_red[tid] = W_ij[tid] * s_z[tid] + W_j_b[tid] * W_ij[F + tid];
    __syncthreads();
    if (tid < 64) s_red[tid] += s_red[tid + 64];
    __syncthreads();
    if (tid < 32) {
        float c = s_red[tid] + s_red[tid + 32];
#pragma unroll
        for (int off = 16; off > 0; off >>= 1)
            c += __shfl_xor_sync(0xffffffffu, c, off);
        if (tid == 0) g_c0 = c;
    }
}

// ---------------------------------------------------------------------------
// Kernel B: R2's measured-best streaming loop (1 row/warp/iter, eager
// branch-free online softmax, 1-ahead prefetch) + fused last-block finalize.
// ---------------------------------------------------------------------------
__global__ void __launch_bounds__(TPB) pass_kernel(
        const float* __restrict__ h_j,
        const float* __restrict__ W_j_w,
        const float* __restrict__ W_j_b,
        float* __restrict__ out) {
    __shared__ __align__(16) float sv[F];
    __shared__ float red_m[WPB];
    __shared__ float red_s[WPB];
    __shared__ float red_u[WPB * F];
    __shared__ float s_mb;

    if (threadIdx.x < F) {
        float v = 0.f;
#pragma unroll
        for (int s = 0; s < 8; s++) v += g_pv[s * F + threadIdx.x];
        sv[threadIdx.x] = v;
    }
    __syncthreads();

    const float c0   = g_c0;
    const int  warp  = threadIdx.x >> 5;
    const int  lane  = threadIdx.x & 31;
    const int  gw    = blockIdx.x * WPB + warp;

    const float4 vv = reinterpret_cast<const float4*>(sv)[lane];
    const float4* __restrict__ hj4 = reinterpret_cast<const float4*>(h_j);

    float m = -1e30f, ssum = 0.f;
    float ux = 0.f, uy = 0.f, uz = 0.f, uw = 0.f;

    int row = gw;
    float4 x = make_float4(0.f, 0.f, 0.f, 0.f);
    if (row < NJ) x = __ldg(hj4 + (size_t)row * 32 + lane);

    while (row < NJ) {
        const int nrow = row + NW;
        float4 xn = x;
        if (nrow < NJ) xn = __ldg(hj4 + (size_t)nrow * 32 + lane);

        float d = x.x * vv.x + x.y * vv.y + x.z * vv.z + x.w * vv.w;
        d += __shfl_xor_sync(0xffffffffu, d, 16);
        d += __shfl_xor_sync(0xffffffffu, d, 8);
        d += __shfl_xor_sync(0xffffffffu, d, 4);
        d += __shfl_xor_sync(0xffffffffu, d, 2);
        d += __shfl_xor_sync(0xffffffffu, d, 1);

        const float s = d + c0;
        const float e = (s > 0.f) ? s : 0.1f * s;

        const float mn    = fmaxf(m, e);
        const float scale = __expf(m - mn);
        const float w     = __expf(e - mn);
        ssum = ssum * scale + w;
        ux   = ux * scale + w * x.x;
        uy   = uy * scale + w * x.y;
        uz   = uz * scale + w * x.z;
        uw   = uw * scale + w * x.w;
        m = mn;

        x = xn;
        row = nrow;
    }

    // ---- block combine ----
    if (lane == 0) { red_m[warp] = m; red_s[warp] = ssum; }
    red_u[warp * F + lane * 4 + 0] = ux;
    red_u[warp * F + lane * 4 + 1] = uy;
    red_u[warp * F + lane * 4 + 2] = uz;
    red_u[warp * F + lane * 4 + 3] = uw;
    __syncthreads();

    if (threadIdx.x == 0) {
        float mb = red_m[0];
#pragma unroll
        for (int w2 = 1; w2 < WPB; w2++) mb = fmaxf(mb, red_m[w2]);
        s_mb = mb;
    }
    __syncthreads();
    const float mb = s_mb;

    const int t = threadIdx.x;
    if (t < F) {
        float acc = 0.f;
#pragma unroll
        for (int w2 = 0; w2 < WPB; w2++)
            acc += __expf(red_m[w2] - mb) * red_u[w2 * F + t];
        g_u[blockIdx.x * F + t] = acc;
    }
    if (t == 0) {
        float sb = 0.f;
#pragma unroll
        for (int w2 = 0; w2 < WPB; w2++) sb += __expf(red_m[w2] - mb) * red_s[w2];
        g_s[blockIdx.x] = sb;
        g_m[blockIdx.x] = mb;
    }
    __syncthreads();

    // ---- last-block fused finalize ----
    __shared__ unsigned int s_last;
    __threadfence();
    if (threadIdx.x == 0)
        s_last = (atomicAdd(&g_cnt, 1u) == (unsigned)(NBLK - 1)) ? 1u : 0u;
    __syncthreads();
    if (!s_last) return;

    __shared__ float sf[NBLK];
    __shared__ float s_pu[2 * F];
    __shared__ __align__(16) float sun[F];
    __shared__ float s_r[WPB];
    __shared__ float s_mg, s_S;

    // global max over NBLK block maxima
    {
        float lm = -1e30f;
        for (int b = t; b < NBLK; b += TPB) lm = fmaxf(lm, g_m[b]);
#pragma unroll
        for (int off = 16; off > 0; off >>= 1)
            lm = fmaxf(lm, __shfl_xor_sync(0xffffffffu, lm, off));
        if (lane == 0) s_r[warp] = lm;
        __syncthreads();
        if (t == 0) {
            float v = s_r[0];
#pragma unroll
            for (int w2 = 1; w2 < WPB; w2++) v = fmaxf(v, s_r[w2]);
            s_mg = v;
        }
        __syncthreads();
    }
    const float mg = s_mg;

    // scale factors + global sum
    {
        float ls = 0.f;
        for (int b = t; b < NBLK; b += TPB) {
            const float fct = __expf(g_m[b] - mg);
            sf[b] = fct;
            ls += fct * g_s[b];
        }
#pragma unroll
        for (int off = 16; off > 0; off >>= 1)
            ls += __shfl_xor_sync(0xffffffffu, ls, off);
        if (lane == 0) s_r[warp] = ls;
        __syncthreads();
        if (t == 0) {
            float v = 0.f;
#pragma unroll
            for (int w2 = 0; w2 < WPB; w2++) v += s_r[w2];
            s_S = v;
        }
        __syncthreads();
    }
    const float S = s_S;

    // combine u partials: 2 slices x 128 features (888 = 2*444), L2-hot
    {
        const int slice = t >> 7;
        const int tf    = t & 127;
        const int b0    = slice * 444;
        float acc = 0.f;
#pragma unroll 4
        for (int k = 0; k < 444; k++)
            acc += sf[b0 + k] * g_u[(b0 + k) * F + tf];
        s_pu[slice * F + tf] = acc;
    }
    __syncthreads();
    if (t < F) sun[t] = (s_pu[t] + s_pu[F + t]) / S;
    __syncthreads();

    // h = W_j_w @ u_norm + b : warp-per-row, 16 rows per warp
    const float4 uv = reinterpret_cast<const float4*>(sun)[lane];
#pragma unroll 4
    for (int r = 0; r < 16; r++) {
        const int f = warp + WPB * r;
        const float4 wrow = reinterpret_cast<const float4*>(W_j_w + f * F)[lane];
        float d = wrow.x*uv.x + wrow.y*uv.y + wrow.z*uv.z + wrow.w*uv.w;
#pragma unroll
        for (int off = 16; off > 0; off >>= 1)
            d += __shfl_xor_sync(0xffffffffu, d, off);
        if (lane == 0) {
            const float h = d + W_j_b[f];
            out[f] = (h > 0.f) ? h : expm1f(h);
        }
    }
}

// ---------------------------------------------------------------------------
extern "C" void kernel_launch(void* const* d_in, const int* in_sizes, int n_in,
                              void* d_out, int out_size) {
    const float* h_i   = (const float*)d_in[0];
    const float* h_j   = (const float*)d_in[1];
    const float* W_i_w = (const float*)d_in[2];
    const float* W_i_b = (const float*)d_in[3];
    const float* W_j_w = (const float*)d_in[4];
    const float* W_j_b = (const float*)d_in[5];
    const float* W_ij  = (const float*)d_in[6];
    float* out = (float*)d_out;

    prep_kernel<<<9, 1024>>>(h_i, W_i_w, W_i_b, W_j_w, W_j_b, W_ij);
    pass_kernel<<<NBLK, TPB>>>(h_j, W_j_w, W_j_b, out);
}

// round 13
// speedup vs baseline: 1.1687x; 1.1683x over previous
#include <cuda_runtime.h>
#include <math.h>

#define NJ    400000         // divisible by 4
#define F     128
#define NBLK  592            // 4 blocks/SM x 148 SMs (one wave); 592 = 2*296
#define TPB   256
#define WPB   (TPB / 32)
#define NW    (NBLK * WPB)

// Scratch (allocation-free rule: __device__ globals)
__device__ float g_pv[8 * F];
__device__ float g_c0;
__device__ float g_m[NBLK];
__device__ float g_s[NBLK];
__device__ float g_u[NBLK * F];
__device__ unsigned int g_cnt;

// ---------------------------------------------------------------------------
// Kernel A: precompute, grid = 9 blocks x 1024 threads (proven ~3us).
// ---------------------------------------------------------------------------
__global__ void __launch_bounds__(1024) prep_kernel(
        const float* __restrict__ h_i,
        const float* __restrict__ W_i_w,
        const float* __restrict__ W_i_b,
        const float* __restrict__ W_j_w,
        const float* __restrict__ W_j_b,
        const float* __restrict__ W_ij) {
    const int tid  = threadIdx.x;
    const int b    = blockIdx.x;

    if (b < 8) {
        __shared__ float s_p[8 * F];
        const int t   = tid & 127;
        const int sub = tid >> 7;
        const int f0  = b * 16 + sub * 2;
        float acc = W_j_w[f0 * F + t]       * W_ij[F + f0]
                  + W_j_w[(f0 + 1) * F + t] * W_ij[F + f0 + 1];
        s_p[sub * F + t] = acc;
        __syncthreads();
        if (tid < F) {
            float v = 0.f;
#pragma unroll
            for (int s = 0; s < 8; s++) v += s_p[s * F + tid];
            g_pv[b * F + tid] = v;
        }
        return;
    }

    __shared__ __align__(16) float s_hi[F];
    __shared__ float s_z[F];
    __shared__ float s_red[F];
    const int wid  = tid >> 5;
    const int lane = tid & 31;

    if (tid == 0) g_cnt = 0u;
    if (tid < F) s_hi[tid] = h_i[tid];
    __syncthreads();

    const float4 hv = reinterpret_cast<const float4*>(s_hi)[lane];
    const float4 w0 = reinterpret_cast<const float4*>(W_i_w + (wid      ) * F)[lane];
    const float4 w1 = reinterpret_cast<const float4*>(W_i_w + (wid + 32 ) * F)[lane];
    const float4 w2 = reinterpret_cast<const float4*>(W_i_w + (wid + 64 ) * F)[lane];
    const float4 w3 = reinterpret_cast<const float4*>(W_i_w + (wid + 96 ) * F)[lane];
    float d0 = w0.x*hv.x + w0.y*hv.y + w0.z*hv.z + w0.w*hv.w;
    float d1 = w1.x*hv.x + w1.y*hv.y + w1.z*hv.z + w1.w*hv.w;
    float d2 = w2.x*hv.x + w2.y*hv.y + w2.z*hv.z + w2.w*hv.w;
    float d3 = w3.x*hv.x + w3.y*hv.y + w3.z*hv.z + w3.w*hv.w;
#pragma unroll
    for (int off = 16; off > 0; off >>= 1) {
        d0 += __shfl_xor_sync(0xffffffffu, d0, off);
        d1 += __shfl_xor_sync(0xffffffffu, d1, off);
        d2 += __shfl_xor_sync(0xffffffffu, d2, off);
        d3 += __shfl_xor_sync(0xffffffffu, d3, off);
    }
    if (lane == 0) {
        s_z[wid     ] = d0 + W_i_b[wid     ];
        s_z[wid + 32] = d1 + W_i_b[wid + 32];
        s_z[wid + 64] = d2 + W_i_b[wid + 64];
        s_z[wid + 96] = d3 + W_i_b[wid + 96];
    }
    __syncthreads();

    if (tid < F) s_red[tid] = W_ij[tid] * s_z[tid] + W_j_b[tid] * W_ij[F + tid];
    __syncthreads();
    if (tid < 64) s_red[tid] += s_red[tid + 64];
    __syncthreads();
    if (tid < 32) {
        float c = s_red[tid] + s_red[tid + 32];
#pragma unroll
        for (int off = 16; off > 0; off >>= 1)
            c += __shfl_xor_sync(0xffffffffu, c, off);
        if (tid == 0) g_c0 = c;
    }
}

// ---------------------------------------------------------------------------
// Kernel B: R7's best-measured loop (4 rows/warp/iter, eager branch-free
// online softmax, 1-group register prefetch) + NEW: L2 prefetch at +2 groups
// so the blocking LDGs hit L2 instead of DRAM. Fused last-block finalize.
// NJ % 4 == 0, so row < NJ implies row+3 < NJ.
// ---------------------------------------------------------------------------
__global__ void __launch_bounds__(TPB, 4) pass_kernel(
        const float* __restrict__ h_j,
        const float* __restrict__ W_j_w,
        const float* __restrict__ W_j_b,
        float* __restrict__ out) {
    __shared__ __align__(16) float sv[F];
    __shared__ float red_m[WPB];
    __shared__ float red_s[WPB];
    __shared__ float red_u[WPB * F];
    __shared__ float s_mb;

    if (threadIdx.x < F) {
        float v = 0.f;
#pragma unroll
        for (int s = 0; s < 8; s++) v += g_pv[s * F + threadIdx.x];
        sv[threadIdx.x] = v;
    }
    __syncthreads();

    const float c0     = g_c0;
    const int   warp   = threadIdx.x >> 5;
    const int   lane   = threadIdx.x & 31;
    const int   gw     = blockIdx.x * WPB + warp;
    const int   stride = NW * 4;

    const float4 vv = reinterpret_cast<const float4*>(sv)[lane];
    const float4* __restrict__ hj4 = reinterpret_cast<const float4*>(h_j);

    float m = -1e30f, ssum = 0.f;
    float ux = 0.f, uy = 0.f, uz = 0.f, uw = 0.f;

    int row = gw * 4;
    float4 x0 = make_float4(0.f,0.f,0.f,0.f), x1 = x0, x2 = x0, x3 = x0;
    if (row < NJ) {
        const float4* p = hj4 + (size_t)row * 32 + lane;
        x0 = __ldg(p);
        x1 = __ldg(p + 32);
        x2 = __ldg(p + 64);
        x3 = __ldg(p + 96);
    }

    while (row < NJ) {
        const int nrow = row + stride;
        float4 xn0 = x0, xn1 = x1, xn2 = x2, xn3 = x3;
        if (nrow < NJ) {
            const float4* p = hj4 + (size_t)nrow * 32 + lane;
            xn0 = __ldg(p);
            xn1 = __ldg(p + 32);
            xn2 = __ldg(p + 64);
            xn3 = __ldg(p + 96);
        }

        // L2 prefetch the group 2 strides ahead (lead ~1 iteration >= DRAM lat)
        {
            const int prow = row + 2 * stride;
            if (prow < NJ) {
                const float4* pp = hj4 + (size_t)prow * 32 + lane;
                asm volatile("prefetch.global.L2 [%0];" :: "l"(pp));
                asm volatile("prefetch.global.L2 [%0];" :: "l"(pp + 32));
                asm volatile("prefetch.global.L2 [%0];" :: "l"(pp + 64));
                asm volatile("prefetch.global.L2 [%0];" :: "l"(pp + 96));
            }
        }

        // 4 independent dot chains
        float d0 = x0.x*vv.x + x0.y*vv.y + x0.z*vv.z + x0.w*vv.w;
        float d1 = x1.x*vv.x + x1.y*vv.y + x1.z*vv.z + x1.w*vv.w;
        float d2 = x2.x*vv.x + x2.y*vv.y + x2.z*vv.z + x2.w*vv.w;
        float d3 = x3.x*vv.x + x3.y*vv.y + x3.z*vv.z + x3.w*vv.w;
#pragma unroll
        for (int off = 16; off > 0; off >>= 1) {
            d0 += __shfl_xor_sync(0xffffffffu, d0, off);
            d1 += __shfl_xor_sync(0xffffffffu, d1, off);
            d2 += __shfl_xor_sync(0xffffffffu, d2, off);
            d3 += __shfl_xor_sync(0xffffffffu, d3, off);
        }

        const float s0 = d0 + c0, s1 = d1 + c0, s2 = d2 + c0, s3 = d3 + c0;
        const float e0 = (s0 > 0.f) ? s0 : 0.1f * s0;
        const float e1 = (s1 > 0.f) ? s1 : 0.1f * s1;
        const float e2 = (s2 > 0.f) ? s2 : 0.1f * s2;
        const float e3 = (s3 > 0.f) ? s3 : 0.1f * s3;

        // eager branch-free online softmax over 4 rows
        const float mn = fmaxf(fmaxf(fmaxf(e0, e1), fmaxf(e2, e3)), m);
        const float scale = __expf(m - mn);
        const float w0 = __expf(e0 - mn);
        const float w1 = __expf(e1 - mn);
        const float w2 = __expf(e2 - mn);
        const float w3 = __expf(e3 - mn);
        ssum = ssum * scale + (w0 + w1) + (w2 + w3);
        ux = ux * scale + w0*x0.x + w1*x1.x + w2*x2.x + w3*x3.x;
        uy = uy * scale + w0*x0.y + w1*x1.y + w2*x2.y + w3*x3.y;
        uz = uz * scale + w0*x0.z + w1*x1.z + w2*x2.z + w3*x3.z;
        uw = uw * scale + w0*x0.w + w1*x1.w + w2*x2.w + w3*x3.w;
        m = mn;

        x0 = xn0; x1 = xn1; x2 = xn2; x3 = xn3;
        row = nrow;
    }

    // ---- block combine ----
    if (lane == 0) { red_m[warp] = m; red_s[warp] = ssum; }
    red_u[warp * F + lane * 4 + 0] = ux;
    red_u[warp * F + lane * 4 + 1] = uy;
    red_u[warp * F + lane * 4 + 2] = uz;
    red_u[warp * F + lane * 4 + 3] = uw;
    __syncthreads();

    if (threadIdx.x == 0) {
        float mb = red_m[0];
#pragma unroll
        for (int w2 = 1; w2 < WPB; w2++) mb = fmaxf(mb, red_m[w2]);
        s_mb = mb;
    }
    __syncthreads();
    const float mb = s_mb;

    const int t = threadIdx.x;
    if (t < F) {
        float acc = 0.f;
#pragma unroll
        for (int w2 = 0; w2 < WPB; w2++)
            acc += __expf(red_m[w2] - mb) * red_u[w2 * F + t];
        g_u[blockIdx.x * F + t] = acc;
    }
    if (t == 0) {
        float sb = 0.f;
#pragma unroll
        for (int w2 = 0; w2 < WPB; w2++) sb += __expf(red_m[w2] - mb) * red_s[w2];
        g_s[blockIdx.x] = sb;
        g_m[blockIdx.x] = mb;
    }
    __syncthreads();

    // ---- last-block fused finalize ----
    __shared__ unsigned int s_last;
    __threadfence();
    if (threadIdx.x == 0)
        s_last = (atomicAdd(&g_cnt, 1u) == (unsigned)(NBLK - 1)) ? 1u : 0u;
    __syncthreads();
    if (!s_last) return;

    __shared__ float sf[NBLK];
    __shared__ float s_pu[2 * F];
    __shared__ __align__(16) float sun[F];
    __shared__ float s_r[WPB];
    __shared__ float s_mg, s_S;

    // global max over NBLK block maxima
    {
        float lm = -1e30f;
        for (int b = t; b < NBLK; b += TPB) lm = fmaxf(lm, g_m[b]);
#pragma unroll
        for (int off = 16; off > 0; off >>= 1)
            lm = fmaxf(lm, __shfl_xor_sync(0xffffffffu, lm, off));
        if (lane == 0) s_r[warp] = lm;
        __syncthreads();
        if (t == 0) {
            float v = s_r[0];
#pragma unroll
            for (int w2 = 1; w2 < WPB; w2++) v = fmaxf(v, s_r[w2]);
            s_mg = v;
        }
        __syncthreads();
    }
    const float mg = s_mg;

    // scale factors + global sum
    {
        float ls = 0.f;
        for (int b = t; b < NBLK; b += TPB) {
            const float fct = __expf(g_m[b] - mg);
            sf[b] = fct;
            ls += fct * g_s[b];
        }
#pragma unroll
        for (int off = 16; off > 0; off >>= 1)
            ls += __shfl_xor_sync(0xffffffffu, ls, off);
        if (lane == 0) s_r[warp] = ls;
        __syncthreads();
        if (t == 0) {
            float v = 0.f;
#pragma unroll
            for (int w2 = 0; w2 < WPB; w2++) v += s_r[w2];
            s_S = v;
        }
        __syncthreads();
    }
    const float S = s_S;

    // combine u partials: 2 slices x 128 features (592 = 2*296), L2-hot
    {
        const int slice = t >> 7;
        const int tf    = t & 127;
        const int b0    = slice * 296;
        float acc = 0.f;
#pragma unroll 4
        for (int k = 0; k < 296; k++)
            acc += sf[b0 + k] * g_u[(b0 + k) * F + tf];
        s_pu[slice * F + tf] = acc;
    }
    __syncthreads();
    if (t < F) sun[t] = (s_pu[t] + s_pu[F + t]) / S;
    __syncthreads();

    // h = W_j_w @ u_norm + b : warp-per-row, 16 rows per warp
    const float4 uv = reinterpret_cast<const float4*>(sun)[lane];
#pragma unroll 4
    for (int r = 0; r < 16; r++) {
        const int f = warp + WPB * r;
        const float4 wrow = reinterpret_cast<const float4*>(W_j_w + f * F)[lane];
        float d = wrow.x*uv.x + wrow.y*uv.y + wrow.z*uv.z + wrow.w*uv.w;
#pragma unroll
        for (int off = 16; off > 0; off >>= 1)
            d += __shfl_xor_sync(0xffffffffu, d, off);
        if (lane == 0) {
            const float h = d + W_j_b[f];
            out[f] = (h > 0.f) ? h : expm1f(h);
        }
    }
}

// ---------------------------------------------------------------------------
extern "C" void kernel_launch(void* const* d_in, const int* in_sizes, int n_in,
                              void* d_out, int out_size) {
    const float* h_i   = (const float*)d_in[0];
    const float* h_j   = (const float*)d_in[1];
    const float* W_i_w = (const float*)d_in[2];
    const float* W_i_b = (const float*)d_in[3];
    const float* W_j_w = (const float*)d_in[4];
    const float* W_j_b = (const float*)d_in[5];
    const float* W_ij  = (const float*)d_in[6];
    float* out = (float*)d_out;

    prep_kernel<<<9, 1024>>>(h_i, W_i_w, W_i_b, W_j_w, W_j_b, W_ij);
    pass_kernel<<<NBLK, TPB>>>(h_j, W_j_w, W_j_b, out);
}

// round 14
// speedup vs baseline: 1.4665x; 1.2547x over previous
#include <cuda_runtime.h>
#include <math.h>

#define NJ    400000         // divisible by 8
#define F     128
#define NBLK  296            // 2 blocks/SM x 148 SMs (one wave); 296 = 2*148
#define TPB   256
#define WPB   (TPB / 32)
#define NW    (NBLK * WPB)   // 2368 warps
#define RPG   8              // rows per warp per iteration

// Scratch (allocation-free rule: __device__ globals)
__device__ float g_pv[8 * F];
__device__ float g_c0;
__device__ float g_m[NBLK];
__device__ float g_s[NBLK];
__device__ float g_u[NBLK * F];
__device__ unsigned int g_cnt;

// ---------------------------------------------------------------------------
// Kernel A: precompute, grid = 9 blocks x 1024 threads (proven ~3us).
// ---------------------------------------------------------------------------
__global__ void __launch_bounds__(1024) prep_kernel(
        const float* __restrict__ h_i,
        const float* __restrict__ W_i_w,
        const float* __restrict__ W_i_b,
        const float* __restrict__ W_j_w,
        const float* __restrict__ W_j_b,
        const float* __restrict__ W_ij) {
    const int tid  = threadIdx.x;
    const int b    = blockIdx.x;

    if (b < 8) {
        __shared__ float s_p[8 * F];
        const int t   = tid & 127;
        const int sub = tid >> 7;
        const int f0  = b * 16 + sub * 2;
        float acc = W_j_w[f0 * F + t]       * W_ij[F + f0]
                  + W_j_w[(f0 + 1) * F + t] * W_ij[F + f0 + 1];
        s_p[sub * F + t] = acc;
        __syncthreads();
        if (tid < F) {
            float v = 0.f;
#pragma unroll
            for (int s = 0; s < 8; s++) v += s_p[s * F + tid];
            g_pv[b * F + tid] = v;
        }
        return;
    }

    __shared__ __align__(16) float s_hi[F];
    __shared__ float s_z[F];
    __shared__ float s_red[F];
    const int wid  = tid >> 5;
    const int lane = tid & 31;

    if (tid == 0) g_cnt = 0u;
    if (tid < F) s_hi[tid] = h_i[tid];
    __syncthreads();

    const float4 hv = reinterpret_cast<const float4*>(s_hi)[lane];
    const float4 w0 = reinterpret_cast<const float4*>(W_i_w + (wid      ) * F)[lane];
    const float4 w1 = reinterpret_cast<const float4*>(W_i_w + (wid + 32 ) * F)[lane];
    const float4 w2 = reinterpret_cast<const float4*>(W_i_w + (wid + 64 ) * F)[lane];
    const float4 w3 = reinterpret_cast<const float4*>(W_i_w + (wid + 96 ) * F)[lane];
    float d0 = w0.x*hv.x + w0.y*hv.y + w0.z*hv.z + w0.w*hv.w;
    float d1 = w1.x*hv.x + w1.y*hv.y + w1.z*hv.z + w1.w*hv.w;
    float d2 = w2.x*hv.x + w2.y*hv.y + w2.z*hv.z + w2.w*hv.w;
    float d3 = w3.x*hv.x + w3.y*hv.y + w3.z*hv.z + w3.w*hv.w;
#pragma unroll
    for (int off = 16; off > 0; off >>= 1) {
        d0 += __shfl_xor_sync(0xffffffffu, d0, off);
        d1 += __shfl_xor_sync(0xffffffffu, d1, off);
        d2 += __shfl_xor_sync(0xffffffffu, d2, off);
        d3 += __shfl_xor_sync(0xffffffffu, d3, off);
    }
    if (lane == 0) {
        s_z[wid     ] = d0 + W_i_b[wid     ];
        s_z[wid + 32] = d1 + W_i_b[wid + 32];
        s_z[wid + 64] = d2 + W_i_b[wid + 64];
        s_z[wid + 96] = d3 + W_i_b[wid + 96];
    }
    __syncthreads();

    if (tid < F) s_red[tid] = W_ij[tid] * s_z[tid] + W_j_b[tid] * W_ij[F + tid];
    __syncthreads();
    if (tid < 64) s_red[tid] += s_red[tid + 64];
    __syncthreads();
    if (tid < 32) {
        float c = s_red[tid] + s_red[tid + 32];
#pragma unroll
        for (int off = 16; off > 0; off >>= 1)
            c += __shfl_xor_sync(0xffffffffu, c, off);
        if (tid == 0) g_c0 = c;
    }
}

// ---------------------------------------------------------------------------
// Kernel B: 8 rows/warp/iteration (4KB in flight via register prefetch),
// streaming __ldcs loads, eager branch-free online softmax,
// fused last-block finalize. NJ % 8 == 0.
// ---------------------------------------------------------------------------
__global__ void __launch_bounds__(TPB, 2) pass_kernel(
        const float* __restrict__ h_j,
        const float* __restrict__ W_j_w,
        const float* __restrict__ W_j_b,
        float* __restrict__ out) {
    __shared__ __align__(16) float sv[F];
    __shared__ float red_m[WPB];
    __shared__ float red_s[WPB];
    __shared__ float red_u[WPB * F];
    __shared__ float s_mb;

    if (threadIdx.x < F) {
        float v = 0.f;
#pragma unroll
        for (int s = 0; s < 8; s++) v += g_pv[s * F + threadIdx.x];
        sv[threadIdx.x] = v;
    }
    __syncthreads();

    const float c0     = g_c0;
    const int   warp   = threadIdx.x >> 5;
    const int   lane   = threadIdx.x & 31;
    const int   gw     = blockIdx.x * WPB + warp;
    const int   stride = NW * RPG;

    const float4 vv = reinterpret_cast<const float4*>(sv)[lane];
    const float4* __restrict__ hj4 = reinterpret_cast<const float4*>(h_j);

    float m = -1e30f, ssum = 0.f;
    float ux = 0.f, uy = 0.f, uz = 0.f, uw = 0.f;

    int row = gw * RPG;
    float4 xa[RPG];
#pragma unroll
    for (int i = 0; i < RPG; i++) xa[i] = make_float4(0.f, 0.f, 0.f, 0.f);
    if (row < NJ) {
        const float4* p = hj4 + (size_t)row * 32 + lane;
#pragma unroll
        for (int i = 0; i < RPG; i++) xa[i] = __ldcs(p + 32 * i);
    }

    while (row < NJ) {
        const int nrow = row + stride;
        float4 xb[RPG];
#pragma unroll
        for (int i = 0; i < RPG; i++) xb[i] = xa[i];
        if (nrow < NJ) {
            const float4* p = hj4 + (size_t)nrow * 32 + lane;
#pragma unroll
            for (int i = 0; i < RPG; i++) xb[i] = __ldcs(p + 32 * i);
        }

        // 8 independent dot chains
        float d[RPG];
#pragma unroll
        for (int i = 0; i < RPG; i++)
            d[i] = xa[i].x*vv.x + xa[i].y*vv.y + xa[i].z*vv.z + xa[i].w*vv.w;
#pragma unroll
        for (int off = 16; off > 0; off >>= 1) {
#pragma unroll
            for (int i = 0; i < RPG; i++)
                d[i] += __shfl_xor_sync(0xffffffffu, d[i], off);
        }

        float e[RPG];
#pragma unroll
        for (int i = 0; i < RPG; i++) {
            const float s = d[i] + c0;
            e[i] = (s > 0.f) ? s : 0.1f * s;
        }

        // eager branch-free online softmax over 8 rows
        float mn = m;
#pragma unroll
        for (int i = 0; i < RPG; i++) mn = fmaxf(mn, e[i]);
        const float scale = __expf(m - mn);
        float w[RPG];
        float wsum = 0.f;
#pragma unroll
        for (int i = 0; i < RPG; i++) { w[i] = __expf(e[i] - mn); wsum += w[i]; }
        ssum = ssum * scale + wsum;
        float ax = 0.f, ay = 0.f, az = 0.f, aw = 0.f;
#pragma unroll
        for (int i = 0; i < RPG; i++) {
            ax += w[i] * xa[i].x;
            ay += w[i] * xa[i].y;
            az += w[i] * xa[i].z;
            aw += w[i] * xa[i].w;
        }
        ux = ux * scale + ax;
        uy = uy * scale + ay;
        uz = uz * scale + az;
        uw = uw * scale + aw;
        m = mn;

#pragma unroll
        for (int i = 0; i < RPG; i++) xa[i] = xb[i];
        row = nrow;
    }

    // ---- block combine ----
    if (lane == 0) { red_m[warp] = m; red_s[warp] = ssum; }
    red_u[warp * F + lane * 4 + 0] = ux;
    red_u[warp * F + lane * 4 + 1] = uy;
    red_u[warp * F + lane * 4 + 2] = uz;
    red_u[warp * F + lane * 4 + 3] = uw;
    __syncthreads();

    if (threadIdx.x == 0) {
        float mb = red_m[0];
#pragma unroll
        for (int w2 = 1; w2 < WPB; w2++) mb = fmaxf(mb, red_m[w2]);
        s_mb = mb;
    }
    __syncthreads();
    const float mb = s_mb;

    const int t = threadIdx.x;
    if (t < F) {
        float acc = 0.f;
#pragma unroll
        for (int w2 = 0; w2 < WPB; w2++)
            acc += __expf(red_m[w2] - mb) * red_u[w2 * F + t];
        g_u[blockIdx.x * F + t] = acc;
    }
    if (t == 0) {
        float sb = 0.f;
#pragma unroll
        for (int w2 = 0; w2 < WPB; w2++) sb += __expf(red_m[w2] - mb) * red_s[w2];
        g_s[blockIdx.x] = sb;
        g_m[blockIdx.x] = mb;
    }
    __syncthreads();

    // ---- last-block fused finalize ----
    __shared__ unsigned int s_last;
    __threadfence();
    if (threadIdx.x == 0)
        s_last = (atomicAdd(&g_cnt, 1u) == (unsigned)(NBLK - 1)) ? 1u : 0u;
    __syncthreads();
    if (!s_last) return;

    __shared__ float sf[NBLK];
    __shared__ float s_pu[2 * F];
    __shared__ __align__(16) float sun[F];
    __shared__ float s_r[WPB];
    __shared__ float s_mg, s_S;

    // global max over NBLK block maxima
    {
        float lm = -1e30f;
        for (int b = t; b < NBLK; b += TPB) lm = fmaxf(lm, g_m[b]);
#pragma unroll
        for (int off = 16; off > 0; off >>= 1)
            lm = fmaxf(lm, __shfl_xor_sync(0xffffffffu, lm, off));
        if (lane == 0) s_r[warp] = lm;
        __syncthreads();
        if (t == 0) {
            float v = s_r[0];
#pragma unroll
            for (int w2 = 1; w2 < WPB; w2++) v = fmaxf(v, s_r[w2]);
            s_mg = v;
        }
        __syncthreads();
    }
    const float mg = s_mg;

    // scale factors + global sum
    {
        float ls = 0.f;
        for (int b = t; b < NBLK; b += TPB) {
            const float fct = __expf(g_m[b] - mg);
            sf[b] = fct;
            ls += fct * g_s[b];
        }
#pragma unroll
        for (int off = 16; off > 0; off >>= 1)
            ls += __shfl_xor_sync(0xffffffffu, ls, off);
        if (lane == 0) s_r[warp] = ls;
        __syncthreads();
        if (t == 0) {
            float v = 0.f;
#pragma unroll
            for (int w2 = 0; w2 < WPB; w2++) v += s_r[w2];
            s_S = v;
        }
        __syncthreads();
    }
    const float S = s_S;

    // combine u partials: 2 slices x 128 features (296 = 2*148), L2-hot
    {
        const int slice = t >> 7;
        const int tf    = t & 127;
        const int b0    = slice * 148;
        float acc = 0.f;
#pragma unroll 4
        for (int k = 0; k < 148; k++)
            acc += sf[b0 + k] * g_u[(b0 + k) * F + tf];
        s_pu[slice * F + tf] = acc;
    }
    __syncthreads();
    if (t < F) sun[t] = (s_pu[t] + s_pu[F + t]) / S;
    __syncthreads();

    // h = W_j_w @ u_norm + b : warp-per-row, 16 rows per warp
    const float4 uv = reinterpret_cast<const float4*>(sun)[lane];
#pragma unroll 4
    for (int r = 0; r < 16; r++) {
        const int f = warp + WPB * r;
        const float4 wrow = reinterpret_cast<const float4*>(W_j_w + f * F)[lane];
        float d = wrow.x*uv.x + wrow.y*uv.y + wrow.z*uv.z + wrow.w*uv.w;
#pragma unroll
        for (int off = 16; off > 0; off >>= 1)
            d += __shfl_xor_sync(0xffffffffu, d, off);
        if (lane == 0) {
            const float h = d + W_j_b[f];
            out[f] = (h > 0.f) ? h : expm1f(h);
        }
    }
}

// ---------------------------------------------------------------------------
extern "C" void kernel_launch(void* const* d_in, const int* in_sizes, int n_in,
                              void* d_out, int out_size) {
    const float* h_i   = (const float*)d_in[0];
    const float* h_j   = (const float*)d_in[1];
    const float* W_i_w = (const float*)d_in[2];
    const float* W_i_b = (const float*)d_in[3];
    const float* W_j_w = (const float*)d_in[4];
    const float* W_j_b = (const float*)d_in[5];
    const float* W_ij  = (const float*)d_in[6];
    float* out = (float*)d_out;

    prep_kernel<<<9, 1024>>>(h_i, W_i_w, W_i_b, W_j_w, W_j_b, W_ij);
    pass_kernel<<<NBLK, TPB>>>(h_j, W_j_w, W_j_b, out);
}